// round 6
// baseline (speedup 1.0000x reference)
#include <cuda_runtime.h>
#include <cstdint>

#define B_  8
#define N_  256
#define DN  64
#define DE  32
#define DC  64
#define DO_ 60

__device__ __align__(16) float g_pr [B_*N_*DC];
__device__ __align__(16) float g_psb[B_*N_*DC];

// ---------------------------------------------------------------------------
// Kernel A: per-node precompute.
// ---------------------------------------------------------------------------
__global__ void precompute_kernel(const float* __restrict__ node,
                                  const float* __restrict__ W_e,
                                  const float* __restrict__ b_e,
                                  const float* __restrict__ W_n,
                                  const float* __restrict__ b_n,
                                  float* __restrict__ out) {
    __shared__ float nrow[DN];
    const int bn = blockIdx.x;
    const int c  = threadIdx.x;              // 0..63
    nrow[c] = node[bn*DN + c];
    __syncthreads();

    float accR = 0.f, accS = 0.f, accO = 0.f;
    #pragma unroll 8
    for (int k = 0; k < DN; k++) {
        float nv = nrow[k];
        accR = fmaf(nv, W_e[(DE      + k)*DC + c], accR);
        accS = fmaf(nv, W_e[(DE + DN + k)*DC + c], accS);
        if (c < DO_) accO = fmaf(nv, W_n[k*DO_ + c], accO);
    }
    g_pr [bn*DC + c] = accR;
    g_psb[bn*DC + c] = accS + b_e[c];
    if (c < DO_) out[bn*DO_ + c] = accO + b_n[c];
}

// ---------------------------------------------------------------------------
// tf32 helpers
// ---------------------------------------------------------------------------
__device__ __forceinline__ uint32_t tf32r(float f) {
    uint32_t u;
    asm("cvt.rna.tf32.f32 %0, %1;" : "=r"(u) : "f"(f));
    return u;
}
__device__ __forceinline__ void mma_1688(float c[4],
                                         uint32_t a0, uint32_t a1, uint32_t a2, uint32_t a3,
                                         uint32_t b0, uint32_t b1) {
    asm volatile("mma.sync.aligned.m16n8k8.row.col.f32.tf32.tf32.f32 "
                 "{%0,%1,%2,%3}, {%4,%5,%6,%7}, {%8,%9}, {%0,%1,%2,%3};"
                 : "+f"(c[0]), "+f"(c[1]), "+f"(c[2]), "+f"(c[3])
                 : "r"(a0), "r"(a1), "r"(a2), "r"(a3), "r"(b0), "r"(b1));
}

#define ESTRIDE 36   // bank = 4g + t  -> conflict-free A-frag loads
#define WSTRIDE 72   // bank = 8t + g  -> conflict-free B-frag loads

// ---------------------------------------------------------------------------
// Kernel B: one CTA per (b, r).  psb+pr folded into MMA accumulator init,
// psb software-pipelined; mt-outer loop for register economy (3 CTAs/SM).
// Static smem: 36864 + 9216 + 2048 + 256 = 48384 B (< 48K static limit).
// ---------------------------------------------------------------------------
__global__ void __launch_bounds__(256, 3) edge_kernel(
    const float* __restrict__ edge_attr,
    const float* __restrict__ adj,
    const float* __restrict__ W_e,
    const float* __restrict__ W_n,
    float* __restrict__ out) {

    __shared__ uint32_t Esm[N_*ESTRIDE];   // 36864 B
    __shared__ uint32_t Wsm[DE*WSTRIDE];   //  9216 B
    __shared__ float red[8*DC];            //  2048 B
    __shared__ float prsm[DC];             //   256 B

    const int tid  = threadIdx.x;
    const int bn   = blockIdx.x;           // b*N + r
    const int b    = bn >> 8;
    const int wid  = tid >> 5;
    const int lane = tid & 31;
    const int g    = lane >> 2;            // group 0..7
    const int t    = lane & 3;             // thread-in-group

    // --- stage E (coalesced float4, tf32-rounded, padded rows) ---
    const float4* esrc = (const float4*)edge_attr + (size_t)bn * (N_*DE/4);
    #pragma unroll
    for (int i = 0; i < 8; i++) {
        int idx = tid + i*256;
        float4 e = esrc[idx];
        int row = idx >> 3, q = idx & 7;
        uint4 u = { tf32r(e.x), tf32r(e.y), tf32r(e.z), tf32r(e.w) };
        *(uint4*)&Esm[row*ESTRIDE + q*4] = u;
    }
    // --- stage W_e[0:32][64] ---
    #pragma unroll
    for (int i = 0; i < 8; i++) {
        int idx = tid + i*256;
        Wsm[(idx >> 6)*WSTRIDE + (idx & 63)] = tf32r(W_e[idx]);
    }
    if (tid < DC) prsm[tid] = g_pr[(size_t)bn*DC + tid];
    __syncthreads();

    const int s0 = wid * 32;
    const float* adjrow = adj + (size_t)bn*N_;

    float ux[8], uy[8];
    #pragma unroll
    for (int nt = 0; nt < 8; nt++) { ux[nt] = 0.f; uy[nt] = 0.f; }

    #pragma unroll
    for (int mt = 0; mt < 2; mt++) {
        const int r0 = s0 + 16*mt + g;

        // A fragments for this m-tile (conflict-free LDS)
        uint32_t afr[4][4];
        #pragma unroll
        for (int ks = 0; ks < 4; ks++) {
            const int k0 = 8*ks + t;
            afr[ks][0] = Esm[(r0    )*ESTRIDE + k0    ];
            afr[ks][1] = Esm[(r0 + 8)*ESTRIDE + k0    ];
            afr[ks][2] = Esm[(r0    )*ESTRIDE + k0 + 4];
            afr[ks][3] = Esm[(r0 + 8)*ESTRIDE + k0 + 4];
        }

        const float a0 = __ldg(adjrow + r0);
        const float a1 = __ldg(adjrow + r0 + 8);

        // psb pointers for this lane's two rows, software-pipelined over nt
        const float* pA = g_psb + ((size_t)b*N_ + r0)*DC + 2*t;
        const float* pB = pA + 8*DC;
        float2 nA = *(const float2*)pA;
        float2 nB = *(const float2*)pB;

        #pragma unroll
        for (int nt = 0; nt < 8; nt++) {
            float2 cA = nA, cB = nB;
            if (nt < 7) {
                nA = *(const float2*)(pA + (nt + 1)*8);
                nB = *(const float2*)(pB + (nt + 1)*8);
            }
            const float2 pr2 = *(const float2*)&prsm[8*nt + 2*t];

            float acc[4] = { cA.x + pr2.x, cA.y + pr2.y,
                             cB.x + pr2.x, cB.y + pr2.y };
            #pragma unroll
            for (int ks = 0; ks < 4; ks++) {
                uint32_t b0 = Wsm[(8*ks + t    )*WSTRIDE + 8*nt + g];
                uint32_t b1 = Wsm[(8*ks + t + 4)*WSTRIDE + 8*nt + g];
                mma_1688(acc, afr[ks][0], afr[ks][1], afr[ks][2], afr[ks][3], b0, b1);
            }
            // adj-masked leaky-relu, accumulate over this lane's rows
            ux[nt] += acc[0] * ((acc[0] >= 0.f) ? a0 : 0.01f*a0);
            uy[nt] += acc[1] * ((acc[1] >= 0.f) ? a0 : 0.01f*a0);
            ux[nt] += acc[2] * ((acc[2] >= 0.f) ? a1 : 0.01f*a1);
            uy[nt] += acc[3] * ((acc[3] >= 0.f) ? a1 : 0.01f*a1);
        }
    }

    // --- deferred cross-lane reduction: butterfly over the 8 groups ---
    #pragma unroll
    for (int nt = 0; nt < 8; nt++) {
        #pragma unroll
        for (int st = 4; st <= 16; st <<= 1) {
            ux[nt] += __shfl_xor_sync(0xffffffffu, ux[nt], st);
            uy[nt] += __shfl_xor_sync(0xffffffffu, uy[nt], st);
        }
    }
    if (lane < 4) {
        #pragma unroll
        for (int nt = 0; nt < 8; nt++)
            *(float2*)&red[wid*DC + 8*nt + 2*t] = make_float2(ux[nt], uy[nt]);
    }
    __syncthreads();

    // --- combine 8 warp partials, fold through W_n[64:128] ---
    if (tid < DC) {
        float a = 0.f;
        #pragma unroll
        for (int w = 0; w < 8; w++) a += red[w*DC + tid];
        prsm[tid] = a;                       // reuse as aggsm
    }
    __syncthreads();
    if (tid < DO_) {
        float sum = out[(size_t)bn*DO_ + tid];
        #pragma unroll 8
        for (int cc = 0; cc < DC; cc++)
            sum = fmaf(prsm[cc], W_n[(DN + cc)*DO_ + tid], sum);
        out[(size_t)bn*DO_ + tid] = sum;
    }
}

// ---------------------------------------------------------------------------
extern "C" void kernel_launch(void* const* d_in, const int* in_sizes, int n_in,
                              void* d_out, int out_size) {
    const float* node = (const float*)d_in[0];
    const float* edge = (const float*)d_in[1];
    const float* adjp = (const float*)d_in[2];
    const float* W_e  = (const float*)d_in[3];
    const float* b_e  = (const float*)d_in[4];
    const float* W_n  = (const float*)d_in[5];
    const float* b_n  = (const float*)d_in[6];
    float* out = (float*)d_out;

    precompute_kernel<<<B_*N_, 64>>>(node, W_e, b_e, W_n, b_n, out);
    edge_kernel<<<B_*N_, 256>>>(edge, adjp, W_e, W_n, out);
}

// round 7
// speedup vs baseline: 1.2069x; 1.2069x over previous
#include <cuda_runtime.h>
#include <cstdint>

#define B_  8
#define N_  256
#define DN  64
#define DE  32
#define DC  64
#define DO_ 60

__device__ __align__(16) float g_pr [B_*N_*DC];
__device__ __align__(16) float g_psb[B_*N_*DC];

// ---------------------------------------------------------------------------
// Kernel A: per-node precompute.
// ---------------------------------------------------------------------------
__global__ void precompute_kernel(const float* __restrict__ node,
                                  const float* __restrict__ W_e,
                                  const float* __restrict__ b_e,
                                  const float* __restrict__ W_n,
                                  const float* __restrict__ b_n,
                                  float* __restrict__ out) {
    __shared__ float nrow[DN];
    const int bn = blockIdx.x;
    const int c  = threadIdx.x;              // 0..63
    nrow[c] = node[bn*DN + c];
    __syncthreads();

    float accR = 0.f, accS = 0.f, accO = 0.f;
    #pragma unroll 8
    for (int k = 0; k < DN; k++) {
        float nv = nrow[k];
        accR = fmaf(nv, W_e[(DE      + k)*DC + c], accR);
        accS = fmaf(nv, W_e[(DE + DN + k)*DC + c], accS);
        if (c < DO_) accO = fmaf(nv, W_n[k*DO_ + c], accO);
    }
    g_pr [bn*DC + c] = accR;
    g_psb[bn*DC + c] = accS + b_e[c];
    if (c < DO_) out[bn*DO_ + c] = accO + b_n[c];
}

// ---------------------------------------------------------------------------
// tf32 helpers
// ---------------------------------------------------------------------------
__device__ __forceinline__ uint32_t tf32r(float f) {
    uint32_t u;
    asm("cvt.rna.tf32.f32 %0, %1;" : "=r"(u) : "f"(f));
    return u;
}
__device__ __forceinline__ void mma_1688(float c[4],
                                         const uint32_t a[4],
                                         uint32_t b0, uint32_t b1) {
    asm volatile("mma.sync.aligned.m16n8k8.row.col.f32.tf32.tf32.f32 "
                 "{%0,%1,%2,%3}, {%4,%5,%6,%7}, {%8,%9}, {%0,%1,%2,%3};"
                 : "+f"(c[0]), "+f"(c[1]), "+f"(c[2]), "+f"(c[3])
                 : "r"(a[0]), "r"(a[1]), "r"(a[2]), "r"(a[3]), "r"(b0), "r"(b1));
}
__device__ __forceinline__ float lrelu_m(float x, float a1, float a001) {
    return x * ((x >= 0.f) ? a1 : a001);
}

#define ESTRIDE 36   // bank = 4g + t  -> conflict-free A-frag loads
#define WSTRIDE 72   // bank = 8t + g  -> conflict-free B-frag loads

// ---------------------------------------------------------------------------
// Kernel B: one CTA per (b, r).  nt-outer loop: A-frags resident, B-frags
// loaded once per nt (conflict-free), psb+pr folded into MMA C-init with a
// 2-deep prefetch pipeline, lrelu folded immediately (acc dies per nt),
// deferred batched shfl reduction.  Static smem 48384 B, 2 CTAs/SM.
// ---------------------------------------------------------------------------
__global__ void __launch_bounds__(256, 2) edge_kernel(
    const float* __restrict__ edge_attr,
    const float* __restrict__ adj,
    const float* __restrict__ W_e,
    const float* __restrict__ W_n,
    float* __restrict__ out) {

    __shared__ uint32_t Esm[N_*ESTRIDE];   // 36864 B
    __shared__ uint32_t Wsm[DE*WSTRIDE];   //  9216 B
    __shared__ float red[8*DC];            //  2048 B
    __shared__ float prsm[DC];             //   256 B

    const int tid  = threadIdx.x;
    const int bn   = blockIdx.x;           // b*N + r
    const int b    = bn >> 8;
    const int wid  = tid >> 5;
    const int lane = tid & 31;
    const int g    = lane >> 2;            // group 0..7
    const int t    = lane & 3;             // thread-in-group

    // --- stage E (coalesced float4, tf32-rounded, padded rows) ---
    const float4* esrc = (const float4*)edge_attr + (size_t)bn * (N_*DE/4);
    #pragma unroll
    for (int i = 0; i < 8; i++) {
        int idx = tid + i*256;
        float4 e = esrc[idx];
        int row = idx >> 3, q = idx & 7;
        uint4 u = { tf32r(e.x), tf32r(e.y), tf32r(e.z), tf32r(e.w) };
        *(uint4*)&Esm[row*ESTRIDE + q*4] = u;
    }
    // --- stage W_e[0:32][64] ---
    #pragma unroll
    for (int i = 0; i < 8; i++) {
        int idx = tid + i*256;
        Wsm[(idx >> 6)*WSTRIDE + (idx & 63)] = tf32r(W_e[idx]);
    }
    if (tid < DC) prsm[tid] = g_pr[(size_t)bn*DC + tid];
    __syncthreads();

    const int s0 = wid * 32;

    // --- A fragments fully resident: afr[mt][ks][4] ---
    uint32_t afr[2][4][4];
    #pragma unroll
    for (int mt = 0; mt < 2; mt++) {
        const int r0 = s0 + 16*mt + g;
        #pragma unroll
        for (int ks = 0; ks < 4; ks++) {
            const int k0 = 8*ks + t;
            afr[mt][ks][0] = Esm[(r0    )*ESTRIDE + k0    ];
            afr[mt][ks][1] = Esm[(r0 + 8)*ESTRIDE + k0    ];
            afr[mt][ks][2] = Esm[(r0    )*ESTRIDE + k0 + 4];
            afr[mt][ks][3] = Esm[(r0 + 8)*ESTRIDE + k0 + 4];
        }
    }

    // --- adj for this lane's 4 rows (j = 2*mt + hf -> row s0+16mt+8hf+g) ---
    const float* adjrow = adj + (size_t)bn*N_;
    float aj[4], aj001[4];
    #pragma unroll
    for (int j = 0; j < 4; j++) {
        aj[j]    = __ldg(adjrow + s0 + 8*j + g);
        aj001[j] = 0.01f * aj[j];
    }

    // --- psb pointers for the 4 rows; 2-deep prefetch pipeline over nt ---
    const float* p[4];
    #pragma unroll
    for (int j = 0; j < 4; j++)
        p[j] = g_psb + ((size_t)b*N_ + s0 + 8*j + g)*DC + 2*t;

    float2 cur[4], nxt[4];
    #pragma unroll
    for (int j = 0; j < 4; j++) { cur[j] = *(const float2*)(p[j]);
                                  nxt[j] = *(const float2*)(p[j] + 8); }

    float ux[8], uy[8];

    #pragma unroll
    for (int nt = 0; nt < 8; nt++) {
        const float2 pr2 = *(const float2*)&prsm[8*nt + 2*t];

        float acc0[4] = { cur[0].x + pr2.x, cur[0].y + pr2.y,
                          cur[1].x + pr2.x, cur[1].y + pr2.y };
        float acc1[4] = { cur[2].x + pr2.x, cur[2].y + pr2.y,
                          cur[3].x + pr2.x, cur[3].y + pr2.y };

        // rotate pipeline, issue nt+2 loads early
        #pragma unroll
        for (int j = 0; j < 4; j++) {
            cur[j] = nxt[j];
            if (nt < 6) nxt[j] = *(const float2*)(p[j] + (nt + 2)*8);
        }

        #pragma unroll
        for (int ks = 0; ks < 4; ks++) {
            uint32_t b0 = Wsm[(8*ks + t    )*WSTRIDE + 8*nt + g];
            uint32_t b1 = Wsm[(8*ks + t + 4)*WSTRIDE + 8*nt + g];
            mma_1688(acc0, afr[0][ks], b0, b1);
            mma_1688(acc1, afr[1][ks], b0, b1);
        }

        ux[nt] = lrelu_m(acc0[0], aj[0], aj001[0]) + lrelu_m(acc0[2], aj[1], aj001[1])
               + lrelu_m(acc1[0], aj[2], aj001[2]) + lrelu_m(acc1[2], aj[3], aj001[3]);
        uy[nt] = lrelu_m(acc0[1], aj[0], aj001[0]) + lrelu_m(acc0[3], aj[1], aj001[1])
               + lrelu_m(acc1[1], aj[2], aj001[2]) + lrelu_m(acc1[3], aj[3], aj001[3]);
    }

    // --- deferred cross-lane reduction: butterfly over the 8 groups ---
    #pragma unroll
    for (int nt = 0; nt < 8; nt++) {
        #pragma unroll
        for (int st = 4; st <= 16; st <<= 1) {
            ux[nt] += __shfl_xor_sync(0xffffffffu, ux[nt], st);
            uy[nt] += __shfl_xor_sync(0xffffffffu, uy[nt], st);
        }
    }
    if (lane < 4) {
        #pragma unroll
        for (int nt = 0; nt < 8; nt++)
            *(float2*)&red[wid*DC + 8*nt + 2*t] = make_float2(ux[nt], uy[nt]);
    }
    __syncthreads();

    // --- combine 8 warp partials, fold through W_n[64:128] ---
    if (tid < DC) {
        float a = 0.f;
        #pragma unroll
        for (int w = 0; w < 8; w++) a += red[w*DC + tid];
        prsm[tid] = a;                       // reuse as aggsm
    }
    __syncthreads();
    if (tid < DO_) {
        float sum = out[(size_t)bn*DO_ + tid];
        #pragma unroll 8
        for (int cc = 0; cc < DC; cc++)
            sum = fmaf(prsm[cc], W_n[(DN + cc)*DO_ + tid], sum);
        out[(size_t)bn*DO_ + tid] = sum;
    }
}

// ---------------------------------------------------------------------------
extern "C" void kernel_launch(void* const* d_in, const int* in_sizes, int n_in,
                              void* d_out, int out_size) {
    const float* node = (const float*)d_in[0];
    const float* edge = (const float*)d_in[1];
    const float* adjp = (const float*)d_in[2];
    const float* W_e  = (const float*)d_in[3];
    const float* b_e  = (const float*)d_in[4];
    const float* W_n  = (const float*)d_in[5];
    const float* b_n  = (const float*)d_in[6];
    float* out = (float*)d_out;

    precompute_kernel<<<B_*N_, 64>>>(node, W_e, b_e, W_n, b_n, out);
    edge_kernel<<<B_*N_, 256>>>(edge, adjp, W_e, W_n, out);
}